// round 8
// baseline (speedup 1.0000x reference)
#include <cuda_runtime.h>

// ---------------------------------------------------------------------------
// TiDHy reference collapses analytically (validated R3-R5, rel_err 1.2e-7):
//   r zeroed each step, r2 stays zero  =>  hypernet/temporal path dead.
//   sl_rhat = (1/B) * sum_{b,t=0..T-1,d} (b_sd[d]-X[b,t,d])^2
//   sl_rbar = (1/B) * sum_{b,t=1..T-1,d} (b_sd[d]-X[b,t,d])^2
//   temp_loss = r2_losses = 0; r0, r2 outputs = zeros.
//
// R6: kill the cross-block combine machinery (ticket atomicInc + threadfence
// + last-block finalize cost ~4.6us in R5). New structure:
//   node 1: cudaMemsetAsync(out, 0)      -- zero tail + scalar bases, makes
//                                           the graph replay-idempotent
//   node 2: reduce kernel; each block leader RED.F32-adds its pre-scaled
//           partial into out[0] / out[1]  -- fire-and-forget, ~1cyc/op
//           throughput at single address, no fence, no ticket, no finalize.
// Float-atomic ordering jitter ~1e-5 relative, threshold is 1e-3.
// ---------------------------------------------------------------------------

static constexpr int Bn   = 128;
static constexpr int T    = 32;
static constexpr int D    = 512;
static constexpr int N4   = Bn * T * D / 4;     // 524288 float4 (8 MB)
static constexpr int BLK  = 256;
static constexpr int GRID = 1024;               // 262144 threads, single wave
static constexpr int HALF = GRID * BLK;         // 262144 = N4/2

__global__ __launch_bounds__(BLK)
void tidhy_reduce_atomic(const float4* __restrict__ X4,
                         const float4* __restrict__ bsd4,
                         float* __restrict__ out)
{
    const int tid = blockIdx.x * BLK + threadIdx.x;

    // Two front-batched coalesced loads per thread.
    // HALF/128 = 2048 ≡ 0 (mod 32): both indices share t and d4.
    float4 x0 = X4[tid];
    float4 x1 = X4[tid + HALF];
    float4 b  = bsd4[tid & (D / 4 - 1)];        // 2 KB, L1-broadcast
    const int t = (tid >> 7) & (T - 1);

    float a0 = b.x - x0.x, a1 = b.y - x0.y, a2 = b.z - x0.z, a3 = b.w - x0.w;
    float c0 = b.x - x1.x, c1 = b.y - x1.y, c2 = b.z - x1.z, c3 = b.w - x1.w;
    float v = a0*a0 + a1*a1 + a2*a2 + a3*a3
            + c0*c0 + c1*c1 + c2*c2 + c3*c3;
    float v0 = (t == 0) ? v : 0.0f;

    // warp tree reduce (two sums pipelined)
    #pragma unroll
    for (int o = 16; o > 0; o >>= 1) {
        v  += __shfl_down_sync(0xffffffffu, v,  o);
        v0 += __shfl_down_sync(0xffffffffu, v0, o);
    }

    __shared__ float sh_all[8], sh_t0[8];
    const int lane = threadIdx.x & 31;
    const int wrp  = threadIdx.x >> 5;
    if (lane == 0) { sh_all[wrp] = v; sh_t0[wrp] = v0; }
    __syncthreads();

    if (wrp != 0) return;

    v  = (lane < BLK / 32) ? sh_all[lane] : 0.0f;
    v0 = (lane < BLK / 32) ? sh_t0[lane]  : 0.0f;
    #pragma unroll
    for (int o = 4; o > 0; o >>= 1) {
        v  += __shfl_down_sync(0x000000ffu, v,  o);
        v0 += __shfl_down_sync(0x000000ffu, v0, o);
    }

    if (lane == 0) {
        constexpr float invB = 1.0f / (float)Bn;
        // fire-and-forget RED.F32: sl_rhat += v/B ; sl_rbar += (v-v0)/B
        atomicAdd(out + 0, v * invB);
        atomicAdd(out + 1, (v - v0) * invB);
        // out[2], out[3], r0, r2 are all zero — handled by the memset node.
    }
}

extern "C" void kernel_launch(void* const* d_in, const int* in_sizes, int n_in,
                              void* d_out, int out_size)
{
    // metadata order: X, rng, W_sd, b_sd, W_h1, b_h1, ln_scale, ln_bias,
    //                 W_h2, b_h2, W_h3, b_h3, temporal
    const float4* X4   = (const float4*)d_in[0];
    const float4* bsd4 = (const float4*)d_in[3];
    float* out = (float*)d_out;

    // Node 1: zero entire output (scalars + r0 + r2). Graph-capturable,
    // allocation-free, and resets the atomic accumulators every replay.
    cudaMemsetAsync(d_out, 0, (size_t)out_size * sizeof(float));

    // Node 2: fused squared-error reduction with RED.F32 scalar combine.
    tidhy_reduce_atomic<<<GRID, BLK>>>(X4, bsd4, out);
}